// round 3
// baseline (speedup 1.0000x reference)
#include <cuda_runtime.h>
#include <stdint.h>

// Problem constants (fixed shapes per reference)
#define N_TOK   32768      // 32 * 1024
#define N_CODE  8192
#define DIM     256
#define QUANT_ELEMS (N_TOK * DIM)   // 8388608

// ---------------- scratch (no allocations allowed) ----------------
__device__ float g_e2[N_CODE];
__device__ int   g_idx[N_TOK];
__device__ float g_part[4096];

// ---------------- Kernel A: codebook squared norms ----------------
__global__ void k_e2(const float* __restrict__ E) {
    int warp = (blockIdx.x << 3) + (threadIdx.x >> 5);
    int lane = threadIdx.x & 31;
    const float* row = E + warp * DIM;
    float s = 0.f;
#pragma unroll
    for (int i = 0; i < 8; i++) {
        float v = row[lane + i * 32];
        s = fmaf(v, v, s);
    }
#pragma unroll
    for (int off = 16; off; off >>= 1)
        s += __shfl_down_sync(0xffffffffu, s, off);
    if (lane == 0) g_e2[warp] = s;
}

// ---------------- Kernel B: fused distance-GEMM + argmin ----------------
// 128x128 tile, 8x8 microtile, BK=8, plain scalar FFMA (no inline asm).
// Grid: N_TOK/128 = 256 blocks of 256 threads. Each block sweeps all 8192 codes.
__global__ __launch_bounds__(256, 2) void k_argmin(
    const float* __restrict__ X, const float* __restrict__ E,
    float* __restrict__ out_idx_f)
{
    __shared__ float As[8][128];   // As[k][m]
    __shared__ float Bs[8][128];   // Bs[k][n]

    const int tid  = threadIdx.x;
    const int tx   = tid & 15;     // col group (codes)
    const int ty   = tid >> 4;     // row group (tokens)
    const int m0   = blockIdx.x * 128;
    const int rowL = tid >> 1;     // 0..127, shared by A/B loaders
    const int ch4  = (tid & 1) * 4;

    const float* Xg = X + (m0 + rowL) * DIM + ch4;

    float minv[8];
    int   mini[8];
#pragma unroll
    for (int r = 0; r < 8; r++) { minv[r] = 3.4e38f; mini[r] = 0; }

    for (int j0 = 0; j0 < N_CODE; j0 += 128) {
        float acc[8][8];
#pragma unroll
        for (int r = 0; r < 8; r++)
#pragma unroll
            for (int c = 0; c < 8; c++) acc[r][c] = 0.f;

        const float* Eg = E + (j0 + rowL) * DIM + ch4;

        for (int k0 = 0; k0 < DIM; k0 += 8) {
            float4 va = *(const float4*)(Xg + k0);
            float4 vb = *(const float4*)(Eg + k0);
            As[ch4 + 0][rowL] = va.x; As[ch4 + 1][rowL] = va.y;
            As[ch4 + 2][rowL] = va.z; As[ch4 + 3][rowL] = va.w;
            Bs[ch4 + 0][rowL] = vb.x; Bs[ch4 + 1][rowL] = vb.y;
            Bs[ch4 + 2][rowL] = vb.z; Bs[ch4 + 3][rowL] = vb.w;
            __syncthreads();

#pragma unroll
            for (int kk = 0; kk < 8; kk++) {
                float4 b0 = *(const float4*)&Bs[kk][tx * 8];
                float4 b1 = *(const float4*)&Bs[kk][tx * 8 + 4];
                float bv[8] = {b0.x, b0.y, b0.z, b0.w, b1.x, b1.y, b1.z, b1.w};
                float4 a0 = *(const float4*)&As[kk][ty * 8];
                float4 a1 = *(const float4*)&As[kk][ty * 8 + 4];
                float av[8] = {a0.x, a0.y, a0.z, a0.w, a1.x, a1.y, a1.z, a1.w};
#pragma unroll
                for (int r = 0; r < 8; r++)
#pragma unroll
                    for (int c = 0; c < 8; c++)
                        acc[r][c] = fmaf(av[r], bv[c], acc[r][c]);
            }
            __syncthreads();
        }

        // epilogue: score = ||e||^2 - 2*dot ; running argmin
        const float* e2p = g_e2 + j0 + tx * 8;
        float e2v[8];
#pragma unroll
        for (int c = 0; c < 8; c++) e2v[c] = __ldg(e2p + c);
#pragma unroll
        for (int r = 0; r < 8; r++) {
#pragma unroll
            for (int c = 0; c < 8; c++) {
                float d = fmaf(-2.0f, acc[r][c], e2v[c]);
                int   i = j0 + tx * 8 + c;
                if (d < minv[r]) { minv[r] = d; mini[r] = i; }
            }
        }
    }

    // reduce argmin across the 16 tx-threads sharing each token row
#pragma unroll
    for (int r = 0; r < 8; r++) {
        float v = minv[r];
        int   i = mini[r];
#pragma unroll
        for (int off = 8; off; off >>= 1) {
            float ov = __shfl_down_sync(0xffffffffu, v, off, 16);
            int   oi = __shfl_down_sync(0xffffffffu, i, off, 16);
            if (ov < v || (ov == v && oi < i)) { v = ov; i = oi; }
        }
        if (tx == 0) {
            int m = m0 + ty * 8 + r;
            g_idx[m] = i;
            out_idx_f[m] = (float)i;   // indices output as float
        }
    }
}

// ---------------- Kernel C: gather + quantized output + loss partials ----------------
// 4096 blocks x 256 threads x 8 elems = 8388608. Each block covers 8 whole tokens.
__global__ void k_gather(const float* __restrict__ X, const float* __restrict__ E,
                         float* __restrict__ outq)
{
    __shared__ float red[256];
    const int tid = threadIdx.x;
    const long base = (long)blockIdx.x * 2048;
    float s = 0.f;
#pragma unroll
    for (int i = 0; i < 8; i++) {
        long e = base + i * 256 + tid;
        int  m = (int)(e >> 8);
        int  d = (int)(e & 255);
        float q = E[g_idx[m] * DIM + d];
        float x = X[e];
        float diff = q - x;
        outq[e] = x + diff;            // straight-through: match reference op order
        s = fmaf(diff, diff, s);
    }
    red[tid] = s;
    __syncthreads();
#pragma unroll
    for (int st = 128; st; st >>= 1) {
        if (tid < st) red[tid] += red[tid + st];
        __syncthreads();
    }
    if (tid == 0) g_part[blockIdx.x] = red[0];
}

// ---------------- Kernel D: deterministic loss reduction ----------------
__global__ void k_loss(float* __restrict__ loss_out) {
    __shared__ float red[256];
    const int tid = threadIdx.x;
    float s = 0.f;
    for (int i = tid; i < 4096; i += 256) s += g_part[i];
    red[tid] = s;
    __syncthreads();
#pragma unroll
    for (int st = 128; st; st >>= 1) {
        if (tid < st) red[tid] += red[tid + st];
        __syncthreads();
    }
    if (tid == 0)
        loss_out[0] = 2.0f * (red[0] / (float)QUANT_ELEMS);
}

// ---------------- launch ----------------
extern "C" void kernel_launch(void* const* d_in, const int* in_sizes, int n_in,
                              void* d_out, int out_size) {
    const float* X = (const float*)d_in[0];   // inputs  (32,1024,256) f32
    const float* E = (const float*)d_in[1];   // embedding (8192,256) f32
    float* out = (float*)d_out;

    float* outq    = out;                 // [0, 8388608): quantized_st
    float* outloss = out + QUANT_ELEMS;   // [8388608]: loss
    float* outidx  = out + QUANT_ELEMS + 1; // [8388609, +32768): indices as f32

    k_e2    <<<N_CODE / 8, 256>>>(E);
    k_argmin<<<N_TOK / 128, 256>>>(X, E, outidx);
    k_gather<<<QUANT_ELEMS / 2048, 256>>>(X, E, outq);
    k_loss  <<<1, 256>>>(outloss);

    (void)in_sizes; (void)n_in; (void)out_size;
}